// round 9
// baseline (speedup 1.0000x reference)
#include <cuda_runtime.h>
#include <cstdint>

// AttentionBlock fused gate kernel — TMA bulk-copy pipeline (cp.async.bulk),
// 3-stage mbarrier double-buffering, compute from SMEM.
// Inputs: xatt[B*L*C], xsaut[B*L*C], W_act[C], b_act[1], W_saut[C], b_saut[1], W2[1], b2[1]
// Output: out[B*L] fp32.  B=64, L=16384, C=64.
//
// Tile = 64 positions = 16KB per tensor. Each block grid-strides over tiles;
// thread 0 keeps 2 tiles in flight via cp.async.bulk (16KB bursts -> long
// sequential DRAM requests); 256 threads (16 groups of 16 lanes) compute the
// dot products from SMEM, 4 positions per group per tile.

#define NEG_SLOPE  0.3f
#define TILE_POS   64
#define TILE_BYTES (TILE_POS * 64 * 4)   // 16384 per tensor
#define STAGES     3
#define NTHREADS   256

// smem layout: [0..48) mbarriers (full[3], empty[3]); buffers at 1024.
#define SMEM_MBAR  0
#define SMEM_BUF   1024
#define STAGE_BYTES (2 * TILE_BYTES)     // A tile + S tile
#define SMEM_TOTAL (SMEM_BUF + STAGES * STAGE_BYTES)

__device__ __forceinline__ uint32_t smem_u32(const void* p) {
    uint32_t a;
    asm("{ .reg .u64 t; cvta.to.shared.u64 t, %1; cvt.u32.u64 %0, t; }"
        : "=r"(a) : "l"(p));
    return a;
}
__device__ __forceinline__ void mbar_init(uint32_t m, uint32_t cnt) {
    asm volatile("mbarrier.init.shared.b64 [%0], %1;" :: "r"(m), "r"(cnt) : "memory");
}
__device__ __forceinline__ void mbar_expect_tx(uint32_t m, uint32_t bytes) {
    asm volatile("mbarrier.arrive.expect_tx.shared.b64 _, [%0], %1;"
                 :: "r"(m), "r"(bytes) : "memory");
}
__device__ __forceinline__ void mbar_arrive(uint32_t m) {
    asm volatile("mbarrier.arrive.shared.b64 _, [%0];" :: "r"(m) : "memory");
}
__device__ __forceinline__ void mbar_wait_acq(uint32_t m, uint32_t parity) {
    uint32_t done;
    asm volatile("{\n\t.reg .pred p;\n\t"
                 "mbarrier.try_wait.parity.acquire.cta.shared::cta.b64 p, [%1], %2;\n\t"
                 "selp.b32 %0, 1, 0, p;\n\t}"
                 : "=r"(done) : "r"(m), "r"(parity) : "memory");
    if (!done) {
        asm volatile("{\n\t.reg .pred P1;\n\t"
                     "W_%=:\n\t"
                     "mbarrier.try_wait.parity.acquire.cta.shared::cta.b64 P1, [%0], %1, 0x989680;\n\t"
                     "@P1 bra.uni D_%=;\n\t"
                     "bra.uni W_%=;\n\t"
                     "D_%=:\n\t}"
                     :: "r"(m), "r"(parity) : "memory");
    }
}
__device__ __forceinline__ void mbar_wait_rlx(uint32_t m, uint32_t parity) {
    uint32_t done;
    asm volatile("{\n\t.reg .pred p;\n\t"
                 "mbarrier.try_wait.parity.relaxed.cta.shared::cta.b64 p, [%1], %2, 0x989680;\n\t"
                 "selp.b32 %0, 1, 0, p;\n\t}"
                 : "=r"(done) : "r"(m), "r"(parity) : "memory");
    if (!done) {
        asm volatile("{\n\t.reg .pred P1;\n\t"
                     "W_%=:\n\t"
                     "mbarrier.try_wait.parity.relaxed.cta.shared::cta.b64 P1, [%0], %1, 0x989680;\n\t"
                     "@P1 bra.uni D_%=;\n\t"
                     "bra.uni W_%=;\n\t"
                     "D_%=:\n\t}"
                     :: "r"(m), "r"(parity) : "memory");
    }
}
__device__ __forceinline__ void bulk_g2s(uint32_t dst, const void* src,
                                         uint32_t bytes, uint32_t mbar) {
    asm volatile("cp.async.bulk.shared::cluster.global.mbarrier::complete_tx::bytes "
                 "[%0], [%1], %2, [%3];"
                 :: "r"(dst), "l"(src), "r"(bytes), "r"(mbar) : "memory");
}

__global__ __launch_bounds__(NTHREADS, 2) void attn_gate_tma_kernel(
    const float* __restrict__ xatt,
    const float* __restrict__ xsaut,
    const float* __restrict__ W_act,
    const float* __restrict__ b_act,
    const float* __restrict__ W_saut,
    const float* __restrict__ b_saut,
    const float* __restrict__ W2,
    const float* __restrict__ b2,
    float* __restrict__ out,
    int ntiles)
{
    extern __shared__ char smem[];
    const uint32_t sbase = smem_u32(smem);
    const int tid    = threadIdx.x;
    const int grp    = tid >> 4;          // 16 groups
    const int lane16 = tid & 15;
    const int bid    = blockIdx.x;
    const int gstr   = gridDim.x;

    // mbarrier addresses
    const uint32_t mb_full  = sbase + SMEM_MBAR;          // 3 x 8B
    const uint32_t mb_empty = sbase + SMEM_MBAR + 24;     // 3 x 8B

    if (tid == 0) {
        #pragma unroll
        for (int s = 0; s < STAGES; s++) {
            mbar_init(mb_full  + s * 8, 1);
            mbar_init(mb_empty + s * 8, NTHREADS);
        }
        asm volatile("fence.proxy.async.shared::cta;" ::: "memory");
    }
    __syncthreads();

    // number of local tiles for this block
    const int n_loc = (ntiles > bid) ? (ntiles - 1 - bid) / gstr + 1 : 0;
    if (n_loc == 0) return;

    const float4 wa = __ldg(reinterpret_cast<const float4*>(W_act)  + lane16);
    const float4 ws = __ldg(reinterpret_cast<const float4*>(W_saut) + lane16);
    const float ba = __ldg(b_act);
    const float bs = __ldg(b_saut);
    const float w2 = __ldg(W2);
    const float bb = __ldg(b2);

    // Producer lambda (thread 0 only): issue tile j's two bulk copies.
    auto produce = [&](int j) {
        const int  s  = j % STAGES;
        const int  r  = j / STAGES;                   // per-stage round
        const long long t = (long long)bid + (long long)j * gstr;
        mbar_wait_rlx(mb_empty + s * 8, (uint32_t)((r + 1) & 1));
        mbar_expect_tx(mb_full + s * 8, 2 * TILE_BYTES);
        const uint32_t dst = sbase + SMEM_BUF + s * STAGE_BYTES;
        bulk_g2s(dst,              xatt  + t * (TILE_POS * 64), TILE_BYTES, mb_full + s * 8);
        bulk_g2s(dst + TILE_BYTES, xsaut + t * (TILE_POS * 64), TILE_BYTES, mb_full + s * 8);
    };

    // Prologue: fill the pipeline (up to STAGES-1 tiles ahead)
    if (tid == 0) {
        if (0 < n_loc) produce(0);
        if (1 < n_loc) produce(1);
    }

    for (int i = 0; i < n_loc; i++) {
        const int s = i % STAGES;
        const int r = i / STAGES;

        if (tid == 0 && (i + 2) < n_loc) produce(i + 2);

        mbar_wait_acq(mb_full + s * 8, (uint32_t)(r & 1));

        const float4* __restrict__ bufA = reinterpret_cast<const float4*>(
            smem + SMEM_BUF + s * STAGE_BYTES);
        const float4* __restrict__ bufS = reinterpret_cast<const float4*>(
            smem + SMEM_BUF + s * STAGE_BYTES + TILE_BYTES);

        const long long t = (long long)bid + (long long)i * gstr;
        float* __restrict__ outp = out + t * TILE_POS;

        // 16 groups x 4 positions each = 64 positions
        float pa[4], ps[4];
        #pragma unroll
        for (int rr = 0; rr < 4; rr++) {
            const int pos = grp + rr * 16;
            const float4 a = bufA[pos * 16 + lane16];
            const float4 sv = bufS[pos * 16 + lane16];
            pa[rr] = a.x * wa.x + a.y * wa.y + a.z * wa.z + a.w * wa.w;
            ps[rr] = sv.x * ws.x + sv.y * ws.y + sv.z * ws.z + sv.w * ws.w;
        }
        #pragma unroll
        for (int off = 8; off > 0; off >>= 1) {
            #pragma unroll
            for (int rr = 0; rr < 4; rr++) {
                pa[rr] += __shfl_xor_sync(0xFFFFFFFFu, pa[rr], off);
                ps[rr] += __shfl_xor_sync(0xFFFFFFFFu, ps[rr], off);
            }
        }
        if (lane16 == 0) {
            #pragma unroll
            for (int rr = 0; rr < 4; rr++) {
                const float xs = ps[rr] + bs;
                float h = (pa[rr] + ba) + xs;
                h = (h >= 0.0f) ? h : NEG_SLOPE * h;
                outp[grp + rr * 16] = xs / (1.0f + __expf(-(h * w2 + bb)));
            }
        }

        // Done reading this stage
        mbar_arrive(mb_empty + s * 8);
    }
}

extern "C" void kernel_launch(void* const* d_in, const int* in_sizes, int n_in,
                              void* d_out, int out_size)
{
    const float* xatt   = (const float*)d_in[0];
    const float* xsaut  = (const float*)d_in[1];
    const float* W_act  = (const float*)d_in[2];
    const float* b_act  = (const float*)d_in[3];
    const float* W_saut = (const float*)d_in[4];
    const float* b_saut = (const float*)d_in[5];
    const float* W2     = (const float*)d_in[6];
    const float* b2     = (const float*)d_in[7];
    float* out = (float*)d_out;

    const int ntiles = out_size / TILE_POS;   // 16384
    const int blocks = 152 * 2;               // 2 CTAs/SM (smem-limited)

    cudaFuncSetAttribute(attn_gate_tma_kernel,
                         cudaFuncAttributeMaxDynamicSharedMemorySize, SMEM_TOTAL);

    attn_gate_tma_kernel<<<blocks, NTHREADS, SMEM_TOTAL>>>(
        xatt, xsaut, W_act, b_act, W_saut, b_saut, W2, b2, out, ntiles);
}

// round 10
// speedup vs baseline: 1.0967x; 1.0967x over previous
#include <cuda_runtime.h>

// AttentionBlock fused gate kernel — split-half two-stream ILP=2 with
// L2::256B fetch-granule hints (best-DRAM% layout from the sweep).
// Inputs: xatt[B*L*C], xsaut[B*L*C], W_act[C], b_act[1], W_saut[C], b_saut[1], W2[1], b2[1]
// Output: out[B*L] fp32.  B=64, L=16384, C=64 -> n_pos = 1,048,576 (half = 524,288).
//
// 16 lanes handle positions (p, p + n_pos/2): 4 front-batched independent
// LDG.128 per thread with 256B L2 fetch granules (sequential access -> no
// overfetch waste, half the L2->DRAM requests per byte).

#define NEG_SLOPE 0.3f

__device__ __forceinline__ float4 ldg_nc_256B(const float4* p) {
    float4 v;
    asm volatile("ld.global.nc.L2::256B.v4.f32 {%0,%1,%2,%3}, [%4];"
                 : "=f"(v.x), "=f"(v.y), "=f"(v.z), "=f"(v.w)
                 : "l"(p));
    return v;
}

__global__ __launch_bounds__(256) void attn_gate_kernel(
    const float* __restrict__ xatt,
    const float* __restrict__ xsaut,
    const float* __restrict__ W_act,
    const float* __restrict__ b_act,
    const float* __restrict__ W_saut,
    const float* __restrict__ b_saut,
    const float* __restrict__ W2,
    const float* __restrict__ b2,
    float* __restrict__ out,
    int half)                              // n_pos / 2
{
    const int gtid   = blockIdx.x * blockDim.x + threadIdx.x;
    const int pos0   = gtid >> 4;          // 16 lanes per position-pair
    const int lane16 = gtid & 15;
    if (pos0 >= half) return;
    const int pos1 = pos0 + half;

    const float4 wa = __ldg(reinterpret_cast<const float4*>(W_act)  + lane16);
    const float4 ws = __ldg(reinterpret_cast<const float4*>(W_saut) + lane16);

    const float4* __restrict__ xa4 = reinterpret_cast<const float4*>(xatt);
    const float4* __restrict__ xs4 = reinterpret_cast<const float4*>(xsaut);

    // Front-batch 4 independent global loads (MLP=4), 4 address streams,
    // 256B L2 fetch granules.
    const float4 a0 = ldg_nc_256B(xa4 + (size_t)pos0 * 16 + lane16);
    const float4 s0 = ldg_nc_256B(xs4 + (size_t)pos0 * 16 + lane16);
    const float4 a1 = ldg_nc_256B(xa4 + (size_t)pos1 * 16 + lane16);
    const float4 s1 = ldg_nc_256B(xs4 + (size_t)pos1 * 16 + lane16);

    float pa0 = a0.x * wa.x + a0.y * wa.y + a0.z * wa.z + a0.w * wa.w;
    float ps0 = s0.x * ws.x + s0.y * ws.y + s0.z * ws.z + s0.w * ws.w;
    float pa1 = a1.x * wa.x + a1.y * wa.y + a1.z * wa.z + a1.w * wa.w;
    float ps1 = s1.x * ws.x + s1.y * ws.y + s1.z * ws.z + s1.w * ws.w;

    #pragma unroll
    for (int off = 8; off > 0; off >>= 1) {
        pa0 += __shfl_xor_sync(0xFFFFFFFFu, pa0, off);
        ps0 += __shfl_xor_sync(0xFFFFFFFFu, ps0, off);
        pa1 += __shfl_xor_sync(0xFFFFFFFFu, pa1, off);
        ps1 += __shfl_xor_sync(0xFFFFFFFFu, ps1, off);
    }

    if (lane16 == 0) {
        const float ba = __ldg(b_act);
        const float bs = __ldg(b_saut);
        const float w2 = __ldg(W2);
        const float bb = __ldg(b2);

        {
            const float xs = ps0 + bs;
            float h = (pa0 + ba) + xs;
            h = (h >= 0.0f) ? h : NEG_SLOPE * h;
            out[pos0] = xs / (1.0f + __expf(-(h * w2 + bb)));
        }
        {
            const float xs = ps1 + bs;
            float h = (pa1 + ba) + xs;
            h = (h >= 0.0f) ? h : NEG_SLOPE * h;
            out[pos1] = xs / (1.0f + __expf(-(h * w2 + bb)));
        }
    }
}

extern "C" void kernel_launch(void* const* d_in, const int* in_sizes, int n_in,
                              void* d_out, int out_size)
{
    const float* xatt   = (const float*)d_in[0];
    const float* xsaut  = (const float*)d_in[1];
    const float* W_act  = (const float*)d_in[2];
    const float* b_act  = (const float*)d_in[3];
    const float* W_saut = (const float*)d_in[4];
    const float* b_saut = (const float*)d_in[5];
    const float* W2     = (const float*)d_in[6];
    const float* b2     = (const float*)d_in[7];
    float* out = (float*)d_out;

    const int half = out_size / 2;           // 524,288
    const int threads = 256;
    const long long total_threads = (long long)half * 16;
    const int blocks = (int)((total_threads + threads - 1) / threads);

    attn_gate_kernel<<<blocks, threads>>>(xatt, xsaut, W_act, b_act,
                                          W_saut, b_saut, W2, b2,
                                          out, half);
}